// round 9
// baseline (speedup 1.0000x reference)
#include <cuda_runtime.h>
#include <cuda_bf16.h>
#include <cstdint>
#include <math.h>

// ---------------- problem constants ----------------
#define BATCH 32
#define CIN   64
#define HWIN  16384
#define COUT  128
#define HO    126
#define WO    126
#define NGRP  16
#define HP    63
#define WP    63
#define NTILE 63
#define GN_N  (8 * HO * WO)

// W tile per tap: SW128 layout [co][32 u32], hi (4096 u32) then lo: 8192 u32 = 32 KB
#define WTAP_U32 8192
#define WTAP_B   32768

// slab: 514 pos x 32 u32 (SW128), per half: 65792 B
#define SLAB_B   65792

// smem layout (bytes):
//  [0,512)        bias (128 f)
//  [512,1024)     sRed  (128 f)
//  [1024,1536)    sRedQ (128 f)
//  [2048,+65536)  W ping-pong: 2 bufs x 32768 B
//  [67584,+65792) slab hi
//  [133376,+65792) slab lo
#define SM_W     2048
#define SM_SLABH 67584
#define SM_SLABL 133376
#define SMEM_TOTAL 199168

#define NTHREADS 512

// ---------------- helpers ----------------
__device__ __forceinline__ uint32_t smem_u32(const void* p) {
    uint32_t a;
    asm("{ .reg .u64 t; cvta.to.shared.u64 t, %1; cvt.u32.u64 %0, t; }" : "=r"(a) : "l"(p));
    return a;
}
#define CP_ASYNC16(dst_u32, src_ptr) \
    asm volatile("cp.async.cg.shared.global [%0], [%1], 16;" :: "r"(dst_u32), "l"(src_ptr) : "memory")
#define CP_COMMIT() asm volatile("cp.async.commit_group;" ::: "memory")
#define CP_WAIT0()  asm volatile("cp.async.wait_group 0;" ::: "memory")

#define LDMX4(r, addr) \
    asm volatile("ldmatrix.sync.aligned.m8n8.x4.shared.b16 {%0,%1,%2,%3}, [%4];" \
        : "=r"((r)[0]), "=r"((r)[1]), "=r"((r)[2]), "=r"((r)[3]) : "r"(addr))

__device__ __forceinline__ void mma16816(float* c, const uint32_t* a, const uint32_t* b) {
    asm volatile(
        "mma.sync.aligned.m16n8k16.row.col.f32.bf16.bf16.f32 "
        "{%0,%1,%2,%3}, {%4,%5,%6,%7}, {%8,%9}, {%0,%1,%2,%3};"
        : "+f"(c[0]), "+f"(c[1]), "+f"(c[2]), "+f"(c[3])
        : "r"(a[0]), "r"(a[1]), "r"(a[2]), "r"(a[3]), "r"(b[0]), "r"(b[1]));
}

// ---------------- device scratch ----------------
__device__ float g_y[(size_t)BATCH * COUT * HO * WO];            // [b][co][h][w]
__device__ __align__(16) uint32_t g_w[9 * WTAP_U32];             // per-tap SW128 bf16 hi/lo
__device__ float g_psum[BATCH * NGRP * NTILE];
__device__ float g_psq [BATCH * NGRP * NTILE];
__device__ float g_mean[BATCH * NGRP];
__device__ float g_rstd[BATCH * NGRP];

// ---------------------------------------------------------------------------
// Prep: conv_w (O,I,3,3) fp32 -> per-tap SW128 [co][k-word] bf16 hi/lo.
// word(co, kw) = co*32 + (kw ^ ((co&7)<<2))
// ---------------------------------------------------------------------------
__global__ void prep_kernel(const float* __restrict__ conv_w) {
    int idx = blockIdx.x * 256 + threadIdx.x;
    if (idx >= 9 * COUT * CIN) return;
    int r   = idx / (COUT * CIN);
    int rem = idx - r * (COUT * CIN);
    int co  = rem >> 6;
    int ci  = rem & 63;
    float w = conv_w[(co * CIN + ci) * 9 + r];
    __nv_bfloat16 h = __float2bfloat16(w);
    __nv_bfloat16 l = __float2bfloat16(w - __bfloat162float(h));
    uint32_t word = (uint32_t)(co * 32) + (((uint32_t)ci >> 1) ^ (uint32_t)((co & 7) << 2));
    unsigned short* gw = (unsigned short*)g_w;
    gw[(r * WTAP_U32 +        word) * 2 + (ci & 1)] = *(unsigned short*)&h;
    gw[(r * WTAP_U32 + 4096 + word) * 2 + (ci & 1)] = *(unsigned short*)&l;
}

// ---------------------------------------------------------------------------
// Conv via mma.sync m16n8k16 bf16, split hi/lo (hh + hl + lh), fp32 acc.
// CTA = (row-pair i, batch b): M=256 pos x N=128 co x K=576.
// 512 threads, 16 warps: 8(M) x 2(N); warp tile 32x64.
// All fragment loads via ldmatrix.x4 on SW128-swizzled smem.
// ---------------------------------------------------------------------------
__global__ __launch_bounds__(NTHREADS, 1)
void conv_kernel(const float* __restrict__ x, const float* __restrict__ conv_b) {
    extern __shared__ char smem[];
    float*    sBias  = (float*)smem;
    float*    sRed   = (float*)(smem + 512);
    float*    sRedQ  = (float*)(smem + 1024);
    uint32_t* sW     = (uint32_t*)(smem + SM_W);

    const int t    = threadIdx.x;
    const int wid  = t >> 5;
    const int lane = t & 31;
    const int g    = lane >> 2;
    const int tl   = lane & 3;
    const int li   = lane & 7;           // ldmatrix row-within-octet
    const int lsel = lane >> 3;          // ldmatrix matrix selector (0..3)
    const int wm   = wid & 7;            // M warp index (0..7)
    const int wn   = wid >> 3;           // N warp index (0..1)
    const int warp_m = wm * 32;
    const int warp_n = wn * 64;
    const int i  = blockIdx.x;           // row pair: output rows 2i, 2i+1
    const int b  = blockIdx.y;
    const int p0 = i * 256;

    const uint32_t sW_addr   = smem_u32(sW);
    const uint32_t slabH_a   = smem_u32(smem + SM_SLABH);

    // prefetch W tap 0 -> buf 0
    {
        const char* src = (const char*)g_w;
        for (int j = t; j < 2048; j += NTHREADS)
            CP_ASYNC16(sW_addr + j * 16, src + j * 16);
        CP_COMMIT();
    }
    if (t < COUT) sBias[t] = conv_b[t];

    // ---- build x slab: 514 pos x 64 ci, bf16 hi/lo, SW128 [pos][k-word] ----
    {
        const float* xb = x + (size_t)b * CIN * HWIN;
        unsigned short* shi = (unsigned short*)(smem + SM_SLABH);
        unsigned short* slo = (unsigned short*)(smem + SM_SLABL);
        for (int idx = t; idx < CIN * 129; idx += NTHREADS) {
            int ci   = idx / 129;
            int gi   = idx - ci * 129;
            int pos0 = gi * 4;
            float v[4];
            if (pos0 + 3 < 514 && p0 + pos0 + 4 <= HWIN) {
                float4 f = *(const float4*)(xb + (size_t)ci * HWIN + p0 + pos0);
                v[0] = f.x; v[1] = f.y; v[2] = f.z; v[3] = f.w;
            } else {
#pragma unroll
                for (int e = 0; e < 4; e++) {
                    int pos = pos0 + e;
                    v[e] = (pos < 514 && p0 + pos < HWIN)
                         ? xb[(size_t)ci * HWIN + p0 + pos] : 0.f;
                }
            }
#pragma unroll
            for (int e = 0; e < 4; e++) {
                int pos = pos0 + e;
                if (pos >= 514) break;
                __nv_bfloat16 h = __float2bfloat16(v[e]);
                __nv_bfloat16 l = __float2bfloat16(v[e] - __bfloat162float(h));
                uint32_t word = (uint32_t)(pos * 32) +
                                (((uint32_t)ci >> 1) ^ (uint32_t)((pos & 7) << 2));
                shi[word * 2 + (ci & 1)] = *(unsigned short*)&h;
                slo[word * 2 + (ci & 1)] = *(unsigned short*)&l;
            }
        }
    }
    CP_WAIT0();
    __syncthreads();

    // B ldmatrix per-lane row constants (independent of tap; base added per buf)
    // np covers n-pair (2np, 2np+1): m0/m1 = octet 2np (chunks c, c+4), m2/m3 = octet 2np+1
    uint32_t bRow[4]; int bKey[4];
#pragma unroll
    for (int np = 0; np < 4; np++) {
        int co = warp_n + ((2 * np + (lsel >> 1)) << 3) + li;
        bRow[np] = (uint32_t)(co * 128);
        bKey[np] = (co & 7) << 2;
    }
    const int bCh = (lsel & 1) << 2;     // chunk word add for B selector
    const int aCh = (lsel >> 1) << 2;    // chunk word add for A selector

    float acc[2][8][4];
#pragma unroll
    for (int m = 0; m < 2; m++)
#pragma unroll
        for (int n = 0; n < 8; n++)
#pragma unroll
            for (int e = 0; e < 4; e++) acc[m][n][e] = 0.f;

    for (int tap = 0; tap < 9; tap++) {
        const int buf = tap & 1;
        if (tap < 8) {   // prefetch next tap into other buffer (safe: synced)
            const char* src = (const char*)(g_w + (tap + 1) * WTAP_U32);
            const uint32_t dst = sW_addr + (buf ^ 1) * WTAP_B;
            for (int j = t; j < 2048; j += NTHREADS)
                CP_ASYNC16(dst + j * 16, src + j * 16);
            CP_COMMIT();
        }
        const uint32_t WH_a = sW_addr + buf * WTAP_B;   // lo at +16384

        const int offp = (tap / 3) * 128 + (tap % 3);
        // A ldmatrix per-lane row constants for this tap
        uint32_t aBase[2]; int aKey[2];
#pragma unroll
        for (int m = 0; m < 2; m++) {
            int row = offp + warp_m + m * 16 + ((lsel & 1) << 3) + li;
            aBase[m] = slabH_a + (uint32_t)(row * 128);
            aKey[m]  = (row & 7) << 2;
        }

#pragma unroll
        for (int kc = 0; kc < 4; kc++) {
            const int kwA = kc * 8 + aCh;
            const int kwB = kc * 8 + bCh;
            uint32_t ah[2][4], al[2][4];
#pragma unroll
            for (int m = 0; m < 2; m++) {
                uint32_t ad = aBase[m] + (uint32_t)((kwA ^ aKey[m]) << 2);
                LDMX4(ah[m], ad);
                LDMX4(al[m], ad + SLAB_B);          // lo slab at fixed offset
            }
#pragma unroll
            for (int np = 0; np < 4; np++) {
                const int n0 = 2 * np, n1 = n0 + 1;
                uint32_t bh[4], bl[4];
                uint32_t bd = WH_a + bRow[np] + (uint32_t)((kwB ^ bKey[np]) << 2);
                LDMX4(bh, bd);
                LDMX4(bl, bd + 16384);              // lo half of W tap
#pragma unroll
                for (int m = 0; m < 2; m++) {
                    mma16816(acc[m][n0], ah[m], bh);        // hi*hi
                    mma16816(acc[m][n0], ah[m], bl);        // hi*lo
                    mma16816(acc[m][n0], al[m], bh);        // lo*hi
                    mma16816(acc[m][n1], ah[m], bh + 2);
                    mma16816(acc[m][n1], ah[m], bl + 2);
                    mma16816(acc[m][n1], al[m], bh + 2);
                }
            }
        }
        if (tap < 8) CP_WAIT0();
        __syncthreads();
    }

    // ---- epilogue: bias, store y, deterministic per-group partials ----
#pragma unroll
    for (int n = 0; n < 8; n++) {
        const int co0 = warp_n + n * 8 + tl * 2;
        const int co1 = co0 + 1;
        const float b0 = sBias[co0];
        const float b1 = sBias[co1];
        float s = 0.f, q = 0.f;
#pragma unroll
        for (int m = 0; m < 2; m++) {
            const int pa = warp_m + m * 16 + g;
            const int pb = pa + 8;
            const int wA = pa & 127, hA = 2 * i + (pa >> 7);
            const int wB = pb & 127, hB = 2 * i + (pb >> 7);
            float v0 = acc[m][n][0] + b0;
            float v1 = acc[m][n][1] + b1;
            float v2 = acc[m][n][2] + b0;
            float v3 = acc[m][n][3] + b1;
            if (wA < 126) {
                size_t iy = ((size_t)(b * COUT + co0) * HO + hA) * WO + wA;
                g_y[iy] = v0;
                g_y[iy + (size_t)HO * WO] = v1;
                s += v0 + v1; q += v0 * v0 + v1 * v1;
            }
            if (wB < 126) {
                size_t iy = ((size_t)(b * COUT + co0) * HO + hB) * WO + wB;
                g_y[iy] = v2;
                g_y[iy + (size_t)HO * WO] = v3;
                s += v2 + v3; q += v2 * v2 + v3 * v3;
            }
        }
#pragma unroll
        for (int o = 16; o > 0; o >>= 1) {
            s += __shfl_xor_sync(0xffffffffu, s, o);
            q += __shfl_xor_sync(0xffffffffu, q, o);
        }
        if (lane == 0) {
            sRed [(wn * 8 + n) * 8 + wm] = s;
            sRedQ[(wn * 8 + n) * 8 + wm] = q;
        }
    }
    __syncthreads();
    if (t < 16) {
        float S = 0.f, Q = 0.f;
#pragma unroll
        for (int k = 0; k < 8; k++) { S += sRed[t * 8 + k]; Q += sRedQ[t * 8 + k]; }
        g_psum[(b * NGRP + t) * NTILE + i] = S;
        g_psq [(b * NGRP + t) * NTILE + i] = Q;
    }
}

// ---------------------------------------------------------------------------
__global__ void stats_kernel() {
    int i = blockIdx.x * blockDim.x + threadIdx.x;
    if (i < BATCH * NGRP) {
        float s = 0.f, q = 0.f;
        const float* ps = g_psum + i * NTILE;
        const float* pq = g_psq  + i * NTILE;
        for (int tl = 0; tl < NTILE; tl++) { s += ps[tl]; q += pq[tl]; }
        const float invN = 1.f / (float)GN_N;
        float mean = s * invN;
        float var  = q * invN - mean * mean;
        g_mean[i] = mean;
        g_rstd[i] = rsqrtf(var + 1e-5f);
    }
}

// ---------------------------------------------------------------------------
__global__ void pool_kernel(const float* __restrict__ gn_w,
                            const float* __restrict__ gn_b,
                            const float* __restrict__ scale,
                            float* __restrict__ out) {
    int idx = blockIdx.x * blockDim.x + threadIdx.x;
    if (idx >= BATCH * COUT * HP * WP) return;
    int ow  = idx % WP;
    int tmp = idx / WP;
    int oh  = tmp % HP;
    tmp    /= HP;
    int c   = tmp % COUT;
    int b   = tmp / COUT;

    const int bg = b * NGRP + (c >> 3);
    const float mean = g_mean[bg];
    const float rstd = g_rstd[bg];
    const float a  = rstd * gn_w[c] * scale[c];
    const float bb = (gn_b[c] - mean * rstd * gn_w[c]) * scale[c];

    const float* yp = g_y + (((size_t)b * COUT + c) * HO + oh * 2) * (size_t)WO + ow * 2;
    float v0 = fmaf(a, yp[0],      bb);
    float v1 = fmaf(a, yp[1],      bb);
    float v2 = fmaf(a, yp[WO],     bb);
    float v3 = fmaf(a, yp[WO + 1], bb);
    float m = fmaxf(fmaxf(v0, v1), fmaxf(v2, v3));
    out[idx] = fminf(fmaxf(m, 0.0f), 1.0f);
}

// ---------------------------------------------------------------------------
extern "C" void kernel_launch(void* const* d_in, const int* in_sizes, int n_in,
                              void* d_out, int out_size) {
    const float* x      = (const float*)d_in[0];
    const float* conv_w = (const float*)d_in[1];
    const float* conv_b = (const float*)d_in[2];
    const float* gn_w   = (const float*)d_in[3];
    const float* gn_b   = (const float*)d_in[4];
    const float* scale  = (const float*)d_in[5];
    float* out = (float*)d_out;

    cudaFuncSetAttribute(conv_kernel, cudaFuncAttributeMaxDynamicSharedMemorySize, SMEM_TOTAL);

    prep_kernel<<<(9 * COUT * CIN + 255) / 256, 256>>>(conv_w);
    conv_kernel<<<dim3(NTILE, BATCH), NTHREADS, SMEM_TOTAL>>>(x, conv_b);
    stats_kernel<<<2, 256>>>();
    const int npool = BATCH * COUT * HP * WP;
    pool_kernel<<<(npool + 255) / 256, 256>>>(gn_w, gn_b, scale, out);
}

// round 11
// speedup vs baseline: 1.8479x; 1.8479x over previous
#include <cuda_runtime.h>
#include <cuda_fp16.h>
#include <cstdint>
#include <math.h>

// ---------------- problem constants ----------------
#define BATCH 32
#define CIN   64
#define HWIN  16384
#define COUT  128
#define HO    126
#define WO    126
#define NGRP  16
#define HP    63
#define WP    63
#define NTILE 63
#define GN_N  (8 * HO * WO)

// W tile per tap: SW128 layout [co][32 u32] fp16: 4096 u32 = 16 KB
#define WTAP_U32 4096
#define WTAP_B   16384

// slab: 514 pos x 32 u32 (SW128) fp16: 65792 B
#define SLAB_B   65792

// smem layout (bytes):
//  [0,512)        bias (128 f)
//  [512,1024)     sRed  (128 f)
//  [1024,1536)    sRedQ (128 f)
//  [2048,+32768)  W ping-pong: 2 bufs x 16384 B
//  [34816,+65792) slab
#define SM_W     2048
#define SM_SLAB  34816
#define SMEM_TOTAL 100608

#define NTHREADS 512

// ---------------- helpers ----------------
__device__ __forceinline__ uint32_t smem_u32(const void* p) {
    uint32_t a;
    asm("{ .reg .u64 t; cvta.to.shared.u64 t, %1; cvt.u32.u64 %0, t; }" : "=r"(a) : "l"(p));
    return a;
}
#define CP_ASYNC16(dst_u32, src_ptr) \
    asm volatile("cp.async.cg.shared.global [%0], [%1], 16;" :: "r"(dst_u32), "l"(src_ptr) : "memory")
#define CP_COMMIT() asm volatile("cp.async.commit_group;" ::: "memory")
#define CP_WAIT0()  asm volatile("cp.async.wait_group 0;" ::: "memory")

#define LDMX4(r, addr) \
    asm volatile("ldmatrix.sync.aligned.m8n8.x4.shared.b16 {%0,%1,%2,%3}, [%4];" \
        : "=r"((r)[0]), "=r"((r)[1]), "=r"((r)[2]), "=r"((r)[3]) : "r"(addr))

__device__ __forceinline__ void mma16816(float* c, const uint32_t* a, const uint32_t* b) {
    asm volatile(
        "mma.sync.aligned.m16n8k16.row.col.f32.f16.f16.f32 "
        "{%0,%1,%2,%3}, {%4,%5,%6,%7}, {%8,%9}, {%0,%1,%2,%3};"
        : "+f"(c[0]), "+f"(c[1]), "+f"(c[2]), "+f"(c[3])
        : "r"(a[0]), "r"(a[1]), "r"(a[2]), "r"(a[3]), "r"(b[0]), "r"(b[1]));
}

// ---------------- device scratch ----------------
__device__ float g_y[(size_t)BATCH * COUT * HO * WO];            // [b][co][h][w]
__device__ __align__(16) uint32_t g_w[9 * WTAP_U32];             // per-tap SW128 fp16
__device__ float g_psum[BATCH * NGRP * NTILE];
__device__ float g_psq [BATCH * NGRP * NTILE];
__device__ float g_mean[BATCH * NGRP];
__device__ float g_rstd[BATCH * NGRP];

// ---------------------------------------------------------------------------
// Prep: conv_w (O,I,3,3) fp32 -> per-tap SW128 [co][k-word] fp16.
// word(co, kw) = co*32 + (kw ^ ((co&7)<<2))
// ---------------------------------------------------------------------------
__global__ void prep_kernel(const float* __restrict__ conv_w) {
    int idx = blockIdx.x * 256 + threadIdx.x;
    if (idx >= 9 * COUT * CIN) return;
    int r   = idx / (COUT * CIN);
    int rem = idx - r * (COUT * CIN);
    int co  = rem >> 6;
    int ci  = rem & 63;
    float w = conv_w[(co * CIN + ci) * 9 + r];
    __half h = __float2half_rn(w);
    uint32_t word = (uint32_t)(co * 32) + (((uint32_t)ci >> 1) ^ (uint32_t)((co & 7) << 2));
    unsigned short* gw = (unsigned short*)g_w;
    gw[(r * WTAP_U32 + word) * 2 + (ci & 1)] = *(unsigned short*)&h;
}

// ---------------------------------------------------------------------------
// Conv via mma.sync m16n8k16 fp16 (single pass), fp32 acc.
// CTA = (row-pair i, batch b): M=256 pos x N=128 co x K=576.
// 512 threads, 16 warps: 8(M) x 2(N); warp tile 32x64.
// All fragment loads via ldmatrix.x4 on SW128-swizzled smem.
// ---------------------------------------------------------------------------
__global__ __launch_bounds__(NTHREADS, 1)
void conv_kernel(const float* __restrict__ x, const float* __restrict__ conv_b) {
    extern __shared__ char smem[];
    float*    sBias  = (float*)smem;
    float*    sRed   = (float*)(smem + 512);
    float*    sRedQ  = (float*)(smem + 1024);
    uint32_t* sW     = (uint32_t*)(smem + SM_W);

    const int t    = threadIdx.x;
    const int wid  = t >> 5;
    const int lane = t & 31;
    const int g    = lane >> 2;
    const int tl   = lane & 3;
    const int li   = lane & 7;           // ldmatrix row-within-octet
    const int lsel = lane >> 3;          // ldmatrix matrix selector (0..3)
    const int wm   = wid & 7;            // M warp index (0..7)
    const int wn   = wid >> 3;           // N warp index (0..1)
    const int warp_m = wm * 32;
    const int warp_n = wn * 64;
    const int i  = blockIdx.x;           // row pair: output rows 2i, 2i+1
    const int b  = blockIdx.y;
    const int p0 = i * 256;

    const uint32_t sW_addr = smem_u32(sW);
    const uint32_t slab_a  = smem_u32(smem + SM_SLAB);

    // prefetch W tap 0 -> buf 0
    {
        const char* src = (const char*)g_w;
        for (int j = t; j < 1024; j += NTHREADS)
            CP_ASYNC16(sW_addr + j * 16, src + j * 16);
        CP_COMMIT();
    }
    if (t < COUT) sBias[t] = conv_b[t];

    // ---- build x slab: 514 pos x 64 ci, fp16, SW128 [pos][k-word] ----
    {
        const float* xb = x + (size_t)b * CIN * HWIN;
        unsigned short* sh = (unsigned short*)(smem + SM_SLAB);
        for (int idx = t; idx < CIN * 129; idx += NTHREADS) {
            int ci   = idx / 129;
            int gi   = idx - ci * 129;
            int pos0 = gi * 4;
            float v[4];
            if (pos0 + 3 < 514 && p0 + pos0 + 4 <= HWIN) {
                float4 f = *(const float4*)(xb + (size_t)ci * HWIN + p0 + pos0);
                v[0] = f.x; v[1] = f.y; v[2] = f.z; v[3] = f.w;
            } else {
#pragma unroll
                for (int e = 0; e < 4; e++) {
                    int pos = pos0 + e;
                    v[e] = (pos < 514 && p0 + pos < HWIN)
                         ? xb[(size_t)ci * HWIN + p0 + pos] : 0.f;
                }
            }
#pragma unroll
            for (int e = 0; e < 4; e++) {
                int pos = pos0 + e;
                if (pos >= 514) break;
                __half h = __float2half_rn(v[e]);
                uint32_t word = (uint32_t)(pos * 32) +
                                (((uint32_t)ci >> 1) ^ (uint32_t)((pos & 7) << 2));
                sh[word * 2 + (ci & 1)] = *(unsigned short*)&h;
            }
        }
    }
    CP_WAIT0();
    __syncthreads();

    // B ldmatrix per-lane row constants (independent of tap; base added per buf)
    uint32_t bRow[4]; int bKey[4];
#pragma unroll
    for (int np = 0; np < 4; np++) {
        int co = warp_n + ((2 * np + (lsel >> 1)) << 3) + li;
        bRow[np] = (uint32_t)(co * 128);
        bKey[np] = (co & 7) << 2;
    }
    const int bCh = (lsel & 1) << 2;     // chunk word add for B selector
    const int aCh = (lsel >> 1) << 2;    // chunk word add for A selector

    float acc[2][8][4];
#pragma unroll
    for (int m = 0; m < 2; m++)
#pragma unroll
        for (int n = 0; n < 8; n++)
#pragma unroll
            for (int e = 0; e < 4; e++) acc[m][n][e] = 0.f;

    for (int tap = 0; tap < 9; tap++) {
        const int buf = tap & 1;
        if (tap < 8) {   // prefetch next tap into other buffer (safe: synced)
            const char* src = (const char*)(g_w + (tap + 1) * WTAP_U32);
            const uint32_t dst = sW_addr + (buf ^ 1) * WTAP_B;
            for (int j = t; j < 1024; j += NTHREADS)
                CP_ASYNC16(dst + j * 16, src + j * 16);
            CP_COMMIT();
        }
        const uint32_t WH_a = sW_addr + buf * WTAP_B;

        const int offp = (tap / 3) * 128 + (tap % 3);
        // A ldmatrix per-lane row constants for this tap
        uint32_t aBase[2]; int aKey[2];
#pragma unroll
        for (int m = 0; m < 2; m++) {
            int row = offp + warp_m + m * 16 + ((lsel & 1) << 3) + li;
            aBase[m] = slab_a + (uint32_t)(row * 128);
            aKey[m]  = (row & 7) << 2;
        }

#pragma unroll
        for (int kc = 0; kc < 4; kc++) {
            const int kwA = kc * 8 + aCh;
            const int kwB = kc * 8 + bCh;
            uint32_t ah[2][4];
#pragma unroll
            for (int m = 0; m < 2; m++)
                LDMX4(ah[m], aBase[m] + (uint32_t)((kwA ^ aKey[m]) << 2));
#pragma unroll
            for (int np = 0; np < 4; np++) {
                const int n0 = 2 * np, n1 = n0 + 1;
                uint32_t bh[4];
                LDMX4(bh, WH_a + bRow[np] + (uint32_t)((kwB ^ bKey[np]) << 2));
#pragma unroll
                for (int m = 0; m < 2; m++) {
                    mma16816(acc[m][n0], ah[m], bh);
                    mma16816(acc[m][n1], ah[m], bh + 2);
                }
            }
        }
        if (tap < 8) CP_WAIT0();
        __syncthreads();
    }

    // ---- epilogue: bias, store y, deterministic per-group partials ----
#pragma unroll
    for (int n = 0; n < 8; n++) {
        const int co0 = warp_n + n * 8 + tl * 2;
        const int co1 = co0 + 1;
        const float b0 = sBias[co0];
        const float b1 = sBias[co1];
        float s = 0.f, q = 0.f;
#pragma unroll
        for (int m = 0; m < 2; m++) {
            const int pa = warp_m + m * 16 + g;
            const int pb = pa + 8;
            const int wA = pa & 127, hA = 2 * i + (pa >> 7);
            const int wB = pb & 127, hB = 2 * i + (pb >> 7);
            float v0 = acc[m][n][0] + b0;
            float v1 = acc[m][n][1] + b1;
            float v2 = acc[m][n][2] + b0;
            float v3 = acc[m][n][3] + b1;
            if (wA < 126) {
                size_t iy = ((size_t)(b * COUT + co0) * HO + hA) * WO + wA;
                g_y[iy] = v0;
                g_y[iy + (size_t)HO * WO] = v1;
                s += v0 + v1; q += v0 * v0 + v1 * v1;
            }
            if (wB < 126) {
                size_t iy = ((size_t)(b * COUT + co0) * HO + hB) * WO + wB;
                g_y[iy] = v2;
                g_y[iy + (size_t)HO * WO] = v3;
                s += v2 + v3; q += v2 * v2 + v3 * v3;
            }
        }
#pragma unroll
        for (int o = 16; o > 0; o >>= 1) {
            s += __shfl_xor_sync(0xffffffffu, s, o);
            q += __shfl_xor_sync(0xffffffffu, q, o);
        }
        if (lane == 0) {
            sRed [(wn * 8 + n) * 8 + wm] = s;
            sRedQ[(wn * 8 + n) * 8 + wm] = q;
        }
    }
    __syncthreads();
    if (t < 16) {
        float S = 0.f, Q = 0.f;
#pragma unroll
        for (int k = 0; k < 8; k++) { S += sRed[t * 8 + k]; Q += sRedQ[t * 8 + k]; }
        g_psum[(b * NGRP + t) * NTILE + i] = S;
        g_psq [(b * NGRP + t) * NTILE + i] = Q;
    }
}

// ---------------------------------------------------------------------------
__global__ void stats_kernel() {
    int i = blockIdx.x * blockDim.x + threadIdx.x;
    if (i < BATCH * NGRP) {
        float s = 0.f, q = 0.f;
        const float* ps = g_psum + i * NTILE;
        const float* pq = g_psq  + i * NTILE;
        for (int tl = 0; tl < NTILE; tl++) { s += ps[tl]; q += pq[tl]; }
        const float invN = 1.f / (float)GN_N;
        float mean = s * invN;
        float var  = q * invN - mean * mean;
        g_mean[i] = mean;
        g_rstd[i] = rsqrtf(var + 1e-5f);
    }
}

// ---------------------------------------------------------------------------
__global__ void pool_kernel(const float* __restrict__ gn_w,
                            const float* __restrict__ gn_b,
                            const float* __restrict__ scale,
                            float* __restrict__ out) {
    int idx = blockIdx.x * blockDim.x + threadIdx.x;
    if (idx >= BATCH * COUT * HP * WP) return;
    int ow  = idx % WP;
    int tmp = idx / WP;
    int oh  = tmp % HP;
    tmp    /= HP;
    int c   = tmp % COUT;
    int b   = tmp / COUT;

    const int bg = b * NGRP + (c >> 3);
    const float mean = g_mean[bg];
    const float rstd = g_rstd[bg];
    const float a  = rstd * gn_w[c] * scale[c];
    const float bb = (gn_b[c] - mean * rstd * gn_w[c]) * scale[c];

    const float* yp = g_y + (((size_t)b * COUT + c) * HO + oh * 2) * (size_t)WO + ow * 2;
    float v0 = fmaf(a, yp[0],      bb);
    float v1 = fmaf(a, yp[1],      bb);
    float v2 = fmaf(a, yp[WO],     bb);
    float v3 = fmaf(a, yp[WO + 1], bb);
    float m = fmaxf(fmaxf(v0, v1), fmaxf(v2, v3));
    out[idx] = fminf(fmaxf(m, 0.0f), 1.0f);
}

// ---------------------------------------------------------------------------
extern "C" void kernel_launch(void* const* d_in, const int* in_sizes, int n_in,
                              void* d_out, int out_size) {
    const float* x      = (const float*)d_in[0];
    const float* conv_w = (const float*)d_in[1];
    const float* conv_b = (const float*)d_in[2];
    const float* gn_w   = (const float*)d_in[3];
    const float* gn_b   = (const float*)d_in[4];
    const float* scale  = (const float*)d_in[5];
    float* out = (float*)d_out;

    cudaFuncSetAttribute(conv_kernel, cudaFuncAttributeMaxDynamicSharedMemorySize, SMEM_TOTAL);

    prep_kernel<<<(9 * COUT * CIN + 255) / 256, 256>>>(conv_w);
    conv_kernel<<<dim3(NTILE, BATCH), NTHREADS, SMEM_TOTAL>>>(x, conv_b);
    stats_kernel<<<2, 256>>>();
    const int npool = BATCH * COUT * HP * WP;
    pool_kernel<<<(npool + 255) / 256, 256>>>(gn_w, gn_b, scale, out);
}

// round 12
// speedup vs baseline: 1.9889x; 1.0763x over previous
#include <cuda_runtime.h>
#include <cuda_fp16.h>
#include <cstdint>
#include <math.h>

// ---------------- problem constants ----------------
#define BATCH 32
#define CIN   64
#define HWIN  16384
#define COUT  128
#define HO    126
#define WO    126
#define NGRP  16
#define HP    63
#define WP    63
#define NTILE 63
#define GN_N  (8 * HO * WO)

// W tile per tap: SW128 layout [co][32 u32] fp16: 4096 u32 = 16 KB; all 9 resident
#define WTAP_U32 4096
#define WTAP_B   16384
#define WALL_B   (9 * WTAP_B)          // 147456

// slab: 514 pos x 32 u32 (SW128) fp16: 65792 B
#define SLAB_B   65792

// smem layout (bytes):
//  [0,512)     bias (128 f)
//  [512,1024)  sRed (128 f)
//  [1024,1536) sRedQ (128 f)
//  [1536,2048) sSgn (128 f)
//  [2048,+147456)  W all taps
//  [149504,+65792) slab
#define SM_W     2048
#define SM_SLAB  149504
#define SMEM_TOTAL 215296

#define NTHREADS 512

// ---------------- helpers ----------------
__device__ __forceinline__ uint32_t smem_u32(const void* p) {
    uint32_t a;
    asm("{ .reg .u64 t; cvta.to.shared.u64 t, %1; cvt.u32.u64 %0, t; }" : "=r"(a) : "l"(p));
    return a;
}
#define CP_ASYNC16(dst_u32, src_ptr) \
    asm volatile("cp.async.cg.shared.global [%0], [%1], 16;" :: "r"(dst_u32), "l"(src_ptr) : "memory")
#define CP_COMMIT() asm volatile("cp.async.commit_group;" ::: "memory")
#define CP_WAIT0()  asm volatile("cp.async.wait_group 0;" ::: "memory")

#define LDMX4(r, addr) \
    asm volatile("ldmatrix.sync.aligned.m8n8.x4.shared.b16 {%0,%1,%2,%3}, [%4];" \
        : "=r"((r)[0]), "=r"((r)[1]), "=r"((r)[2]), "=r"((r)[3]) : "r"(addr))

__device__ __forceinline__ void mma16816(float* c, const uint32_t* a, const uint32_t* b) {
    asm volatile(
        "mma.sync.aligned.m16n8k16.row.col.f32.f16.f16.f32 "
        "{%0,%1,%2,%3}, {%4,%5,%6,%7}, {%8,%9}, {%0,%1,%2,%3};"
        : "+f"(c[0]), "+f"(c[1]), "+f"(c[2]), "+f"(c[3])
        : "r"(a[0]), "r"(a[1]), "r"(a[2]), "r"(a[3]), "r"(b[0]), "r"(b[1]));
}

// ---------------- device scratch ----------------
// per-(b,co,h) width-pair extremes (max if gn_w*scale>=0 else min): [b][co][126][63]
__device__ float g_mw[(size_t)BATCH * COUT * HO * WP];
__device__ __align__(16) uint32_t g_w[9 * WTAP_U32];             // per-tap SW128 fp16
__device__ float g_psum[BATCH * NGRP * NTILE];
__device__ float g_psq [BATCH * NGRP * NTILE];
__device__ float g_mean[BATCH * NGRP];
__device__ float g_rstd[BATCH * NGRP];

// ---------------------------------------------------------------------------
// Prep: conv_w (O,I,3,3) fp32 -> per-tap SW128 [co][k-word] fp16.
// word(co, kw) = co*32 + (kw ^ ((co&7)<<2))
// ---------------------------------------------------------------------------
__global__ void prep_kernel(const float* __restrict__ conv_w) {
    int idx = blockIdx.x * 256 + threadIdx.x;
    if (idx >= 9 * COUT * CIN) return;
    int r   = idx / (COUT * CIN);
    int rem = idx - r * (COUT * CIN);
    int co  = rem >> 6;
    int ci  = rem & 63;
    float w = conv_w[(co * CIN + ci) * 9 + r];
    __half h = __float2half_rn(w);
    uint32_t word = (uint32_t)(co * 32) + (((uint32_t)ci >> 1) ^ (uint32_t)((co & 7) << 2));
    unsigned short* gw = (unsigned short*)g_w;
    gw[(r * WTAP_U32 + word) * 2 + (ci & 1)] = *(unsigned short*)&h;
}

// ---------------------------------------------------------------------------
// Conv via mma.sync m16n8k16 fp16 (single pass), fp32 acc.
// CTA = (row-pair i, batch b): M=256 pos x N=128 co x K=576.
// 512 threads, 16 warps: 8(M) x 2(N); warp tile 32x64.
// All 9 W taps smem-resident -> barrier-free mainloop.
// Epilogue: bias, GN partials, width-pair extreme -> g_mw (pool folded).
// ---------------------------------------------------------------------------
__global__ __launch_bounds__(NTHREADS, 1)
void conv_kernel(const float* __restrict__ x, const float* __restrict__ conv_b,
                 const float* __restrict__ gn_w, const float* __restrict__ scale) {
    extern __shared__ char smem[];
    float*    sBias  = (float*)smem;
    float*    sRed   = (float*)(smem + 512);
    float*    sRedQ  = (float*)(smem + 1024);
    float*    sSgn   = (float*)(smem + 1536);
    uint32_t* sW     = (uint32_t*)(smem + SM_W);

    const int t    = threadIdx.x;
    const int wid  = t >> 5;
    const int lane = t & 31;
    const int g    = lane >> 2;
    const int tl   = lane & 3;
    const int li   = lane & 7;           // ldmatrix row-within-octet
    const int lsel = lane >> 3;          // ldmatrix matrix selector (0..3)
    const int wm   = wid & 7;            // M warp index (0..7)
    const int wn   = wid >> 3;           // N warp index (0..1)
    const int warp_m = wm * 32;
    const int warp_n = wn * 64;
    const int i  = blockIdx.x;           // row pair: output rows 2i, 2i+1
    const int b  = blockIdx.y;
    const int p0 = i * 256;

    const uint32_t sW_addr = smem_u32(sW);
    const uint32_t slab_a  = smem_u32(smem + SM_SLAB);

    // load ALL 9 W taps (144 KB) via cp.async
    {
        const char* src = (const char*)g_w;
        for (int j = t; j < WALL_B / 16; j += NTHREADS)
            CP_ASYNC16(sW_addr + j * 16, src + j * 16);
        CP_COMMIT();
    }
    if (t < COUT) {
        sBias[t] = conv_b[t];
        sSgn[t]  = gn_w[t] * scale[t];
    }

    // ---- build x slab: 514 pos x 64 ci, fp16, SW128 [pos][k-word] ----
    {
        const float* xb = x + (size_t)b * CIN * HWIN;
        unsigned short* sh = (unsigned short*)(smem + SM_SLAB);
        for (int idx = t; idx < CIN * 129; idx += NTHREADS) {
            int ci   = idx / 129;
            int gi   = idx - ci * 129;
            int pos0 = gi * 4;
            float v[4];
            if (pos0 + 3 < 514 && p0 + pos0 + 4 <= HWIN) {
                float4 f = *(const float4*)(xb + (size_t)ci * HWIN + p0 + pos0);
                v[0] = f.x; v[1] = f.y; v[2] = f.z; v[3] = f.w;
            } else {
#pragma unroll
                for (int e = 0; e < 4; e++) {
                    int pos = pos0 + e;
                    v[e] = (pos < 514 && p0 + pos < HWIN)
                         ? xb[(size_t)ci * HWIN + p0 + pos] : 0.f;
                }
            }
#pragma unroll
            for (int e = 0; e < 4; e++) {
                int pos = pos0 + e;
                if (pos >= 514) break;
                __half h = __float2half_rn(v[e]);
                uint32_t word = (uint32_t)(pos * 32) +
                                (((uint32_t)ci >> 1) ^ (uint32_t)((pos & 7) << 2));
                sh[word * 2 + (ci & 1)] = *(unsigned short*)&h;
            }
        }
    }
    CP_WAIT0();
    __syncthreads();                     // the only barrier before the epilogue

    // B ldmatrix per-lane row constants
    uint32_t bRow[4]; int bKey[4];
#pragma unroll
    for (int np = 0; np < 4; np++) {
        int co = warp_n + ((2 * np + (lsel >> 1)) << 3) + li;
        bRow[np] = (uint32_t)(co * 128);
        bKey[np] = (co & 7) << 2;
    }
    const int bCh = (lsel & 1) << 2;     // chunk word add for B selector
    const int aCh = (lsel >> 1) << 2;    // chunk word add for A selector

    float acc[2][8][4];
#pragma unroll
    for (int m = 0; m < 2; m++)
#pragma unroll
        for (int n = 0; n < 8; n++)
#pragma unroll
            for (int e = 0; e < 4; e++) acc[m][n][e] = 0.f;

#pragma unroll
    for (int tap = 0; tap < 9; tap++) {
        const uint32_t WH_a = sW_addr + tap * WTAP_B;
        const int offp = (tap / 3) * 128 + (tap % 3);
        uint32_t aBase[2]; int aKey[2];
#pragma unroll
        for (int m = 0; m < 2; m++) {
            int row = offp + warp_m + m * 16 + ((lsel & 1) << 3) + li;
            aBase[m] = slab_a + (uint32_t)(row * 128);
            aKey[m]  = (row & 7) << 2;
        }
#pragma unroll
        for (int kc = 0; kc < 4; kc++) {
            const int kwA = kc * 8 + aCh;
            const int kwB = kc * 8 + bCh;
            uint32_t ah[2][4];
#pragma unroll
            for (int m = 0; m < 2; m++)
                LDMX4(ah[m], aBase[m] + (uint32_t)((kwA ^ aKey[m]) << 2));
#pragma unroll
            for (int np = 0; np < 4; np++) {
                const int n0 = 2 * np, n1 = n0 + 1;
                uint32_t bh[4];
                LDMX4(bh, WH_a + bRow[np] + (uint32_t)((kwB ^ bKey[np]) << 2));
#pragma unroll
                for (int m = 0; m < 2; m++) {
                    mma16816(acc[m][n0], ah[m], bh);
                    mma16816(acc[m][n1], ah[m], bh + 2);
                }
            }
        }
    }

    // ---- epilogue: bias, GN partials, width-pair extremes -> g_mw ----
    const bool gEven = ((g & 1) == 0);
#pragma unroll
    for (int n = 0; n < 8; n++) {
        const int co0 = warp_n + n * 8 + tl * 2;
        const int co1 = co0 + 1;
        const float b0 = sBias[co0];
        const float b1 = sBias[co1];
        const bool mx0 = (sSgn[co0] >= 0.f);
        const bool mx1 = (sSgn[co1] >= 0.f);
        float s = 0.f, q = 0.f;
#pragma unroll
        for (int m = 0; m < 2; m++) {
            const int pa = warp_m + m * 16 + g;
            const int pb = pa + 8;
            const int wA = pa & 127, hA = 2 * i + (pa >> 7);
            const int wB = pb & 127;
            float v0 = acc[m][n][0] + b0;
            float v1 = acc[m][n][1] + b1;
            float v2 = acc[m][n][2] + b0;
            float v3 = acc[m][n][3] + b1;
            // exchange with the adjacent-w lane (g ^ 1 -> lane ^ 4)
            float p0v = __shfl_xor_sync(0xffffffffu, v0, 4);
            float p1v = __shfl_xor_sync(0xffffffffu, v1, 4);
            float p2v = __shfl_xor_sync(0xffffffffu, v2, 4);
            float p3v = __shfl_xor_sync(0xffffffffu, v3, 4);
            if (wA < 126) { s += v0 + v1; q += v0 * v0 + v1 * v1; }
            if (wB < 126) { s += v2 + v3; q += v2 * v2 + v3 * v3; }
            if (gEven) {
                const size_t rowBase0 = ((size_t)(b * COUT + co0) * HO + hA) * WP;
                const size_t rowBase1 = ((size_t)(b * COUT + co1) * HO + hA) * WP;
                if (wA < 126) {
                    float e0 = mx0 ? fmaxf(v0, p0v) : fminf(v0, p0v);
                    float e1 = mx1 ? fmaxf(v1, p1v) : fminf(v1, p1v);
                    g_mw[rowBase0 + (wA >> 1)] = e0;
                    g_mw[rowBase1 + (wA >> 1)] = e1;
                }
                if (wB < 126) {
                    float e2 = mx0 ? fmaxf(v2, p2v) : fminf(v2, p2v);
                    float e3 = mx1 ? fmaxf(v3, p3v) : fminf(v3, p3v);
                    g_mw[rowBase0 + (wB >> 1)] = e2;
                    g_mw[rowBase1 + (wB >> 1)] = e3;
                }
            }
        }
#pragma unroll
        for (int o = 16; o > 0; o >>= 1) {
            s += __shfl_xor_sync(0xffffffffu, s, o);
            q += __shfl_xor_sync(0xffffffffu, q, o);
        }
        if (lane == 0) {
            sRed [(wn * 8 + n) * 8 + wm] = s;
            sRedQ[(wn * 8 + n) * 8 + wm] = q;
        }
    }
    __syncthreads();
    if (t < 16) {
        float S = 0.f, Q = 0.f;
#pragma unroll
        for (int k = 0; k < 8; k++) { S += sRed[t * 8 + k]; Q += sRedQ[t * 8 + k]; }
        g_psum[(b * NGRP + t) * NTILE + i] = S;
        g_psq [(b * NGRP + t) * NTILE + i] = Q;
    }
}

// ---------------------------------------------------------------------------
__global__ void stats_kernel() {
    int i = blockIdx.x * blockDim.x + threadIdx.x;
    if (i < BATCH * NGRP) {
        float s = 0.f, q = 0.f;
        const float* ps = g_psum + i * NTILE;
        const float* pq = g_psq  + i * NTILE;
        for (int tl = 0; tl < NTILE; tl++) { s += ps[tl]; q += pq[tl]; }
        const float invN = 1.f / (float)GN_N;
        float mean = s * invN;
        float var  = q * invN - mean * mean;
        g_mean[i] = mean;
        g_rstd[i] = rsqrtf(var + 1e-5f);
    }
}

// ---------------------------------------------------------------------------
// Pool: read 2 width-pair extremes (rows 2oh, 2oh+1), affine, max, clamp.
// mw holds the correctly-signed extreme, so max of the two affine values is
// exactly the window max of a*y+b.
// ---------------------------------------------------------------------------
__global__ void pool_kernel(const float* __restrict__ gn_w,
                            const float* __restrict__ gn_b,
                            const float* __restrict__ scale,
                            float* __restrict__ out) {
    int idx = blockIdx.x * blockDim.x + threadIdx.x;
    if (idx >= BATCH * COUT * HP * WP) return;
    int ow  = idx % WP;
    int tmp = idx / WP;
    int oh  = tmp % HP;
    tmp    /= HP;
    int c   = tmp % COUT;
    int b   = tmp / COUT;

    const int bg = b * NGRP + (c >> 3);
    const float mean = g_mean[bg];
    const float rstd = g_rstd[bg];
    const float a  = rstd * gn_w[c] * scale[c];
    const float bb = (gn_b[c] - mean * rstd * gn_w[c]) * scale[c];

    const float* mp = g_mw + ((size_t)(b * COUT + c) * HO + oh * 2) * (size_t)WP + ow;
    float v0 = fmaf(a, mp[0],  bb);
    float v1 = fmaf(a, mp[WP], bb);
    float m = fmaxf(v0, v1);
    out[idx] = fminf(fmaxf(m, 0.0f), 1.0f);
}

// ---------------------------------------------------------------------------
extern "C" void kernel_launch(void* const* d_in, const int* in_sizes, int n_in,
                              void* d_out, int out_size) {
    const float* x      = (const float*)d_in[0];
    const float* conv_w = (const float*)d_in[1];
    const float* conv_b = (const float*)d_in[2];
    const float* gn_w   = (const float*)d_in[3];
    const float* gn_b   = (const float*)d_in[4];
    const float* scale  = (const float*)d_in[5];
    float* out = (float*)d_out;

    cudaFuncSetAttribute(conv_kernel, cudaFuncAttributeMaxDynamicSharedMemorySize, SMEM_TOTAL);

    prep_kernel<<<(9 * COUT * CIN + 255) / 256, 256>>>(conv_w);
    conv_kernel<<<dim3(NTILE, BATCH), NTHREADS, SMEM_TOTAL>>>(x, conv_b, gn_w, scale);
    stats_kernel<<<2, 256>>>();
    const int npool = BATCH * COUT * HP * WP;
    pool_kernel<<<(npool + 255) / 256, 256>>>(gn_w, gn_b, scale, out);
}